// round 2
// baseline (speedup 1.0000x reference)
#include <cuda_runtime.h>

#define DIM 128
#define NLAYERS 4
#define PAD 132
typedef unsigned long long u64;

// Scratch (device globals; no allocation allowed)
__device__ float g_Ur[DIM * DIM];
__device__ float g_Ui[DIM * DIM];
__device__ float g_A[DIM * DIM];

__device__ __forceinline__ u64 ffma2(u64 a, u64 b, u64 c) {
    u64 d;
    asm("fma.rn.f32x2 %0, %1, %2, %3;" : "=l"(d) : "l"(a), "l"(b), "l"(c));
    return d;
}
__device__ __forceinline__ u64 dup2(float v) {
    u64 d; unsigned u = __float_as_uint(v);
    asm("mov.b64 %0, {%1, %1};" : "=l"(d) : "r"(u));
    return d;
}

// ---------------------------------------------------------------------------
// Kernel 1: build U (128 columns; block j simulates column j of the circuit)
// qubit w <-> bit (6-w) of the linear index.
// ---------------------------------------------------------------------------
__global__ void build_u_kernel(const float* __restrict__ w) {
    __shared__ float sr[DIM], si[DIM];
    const int t = threadIdx.x;
    const int j = blockIdx.x;
    sr[t] = (t == j) ? 1.0f : 0.0f;
    si[t] = 0.0f;
    __syncthreads();

    for (int l = 0; l < NLAYERS; l++) {
        // Rot(phi, theta, omega) on each wire
        for (int q = 0; q < 7; q++) {
            const float phi = w[(l * 7 + q) * 3 + 0];
            const float th  = w[(l * 7 + q) * 3 + 1];
            const float om  = w[(l * 7 + q) * 3 + 2];
            float s, c; sincosf(0.5f * th, &s, &c);
            float sa, ca, sb, cb;
            sincosf(0.5f * (phi + om), &sa, &ca);
            sincosf(0.5f * (phi - om), &sb, &cb);
            // U00=(ca*c,-sa*c) U01=(-cb*s,-sb*s) U10=(cb*s,-sb*s) U11=(ca*c,sa*c)
            const float u00r =  ca * c, u00i = -sa * c;
            const float u01r = -cb * s, u01i = -sb * s;
            const float u10r =  cb * s, u10i = -sb * s;
            const float u11r =  ca * c, u11i =  sa * c;
            const int bit = 1 << (6 - q);
            if (!(t & bit)) {
                const int i1 = t | bit;
                const float a0r = sr[t],  a0i = si[t];
                const float a1r = sr[i1], a1i = si[i1];
                sr[t]  = u00r * a0r - u00i * a0i + u01r * a1r - u01i * a1i;
                si[t]  = u00r * a0i + u00i * a0r + u01r * a1i + u01i * a1r;
                sr[i1] = u10r * a0r - u10i * a0i + u11r * a1r - u11i * a1i;
                si[i1] = u10r * a0i + u10i * a0r + u11r * a1i + u11i * a1r;
            }
            __syncthreads();
        }
        // CNOT ring, range r = (l % 6) + 1
        const int r = (l % 6) + 1;
        for (int q = 0; q < 7; q++) {
            const int tq = (q + r) % 7;
            const int cbit = 1 << (6 - q);
            const int tbit = 1 << (6 - tq);
            if ((t & cbit) && !(t & tbit)) {
                const int i1 = t | tbit;
                const float tr = sr[t], ti = si[t];
                sr[t] = sr[i1]; si[t] = si[i1];
                sr[i1] = tr;    si[i1] = ti;
            }
            __syncthreads();
        }
    }
    g_Ur[t * DIM + j] = sr[t];
    g_Ui[t * DIM + j] = si[t];
}

// ---------------------------------------------------------------------------
// Kernel 2: A[i][j] = sum_k sign(k) * (Ur[k][i]Ur[k][j] + Ui[k][i]Ui[k][j])
// sign mask 0x41 = (1<<6)|(1<<0)  (Z on qubit 0 and qubit 6)
// ---------------------------------------------------------------------------
__global__ void build_a_kernel() {
    const int i = blockIdx.x;
    const int j = threadIdx.x;
    float acc = 0.0f;
    for (int k = 0; k < DIM; k++) {
        const float sgn = (__popc(k & 0x41) & 1) ? -1.0f : 1.0f;
        acc += sgn * (g_Ur[k * DIM + i] * g_Ur[k * DIM + j] +
                      g_Ui[k * DIM + i] * g_Ui[k * DIM + j]);
    }
    g_A[i * DIM + j] = acc;
}

// ---------------------------------------------------------------------------
// Kernel 3: fused quadratic form.  Block = 128 batch rows.
// out[n] = (x_n^T A x_n) / (x_n . x_n)
// FFMA2 (f32x2) packed over row pairs; A and X^T fully SMEM-resident.
// ---------------------------------------------------------------------------
extern __shared__ float smem[];

__global__ __launch_bounds__(256, 1)
void vqa_main_kernel(const float* __restrict__ X, float* __restrict__ out) {
    float* XsT  = smem;                  // [128 k][PAD r]  (transposed X tile)
    float* As   = smem + DIM * PAD;      // [128 k][PAD c]
    float* redv = As + DIM * PAD;        // [128 r][16 tx]
    float* redn = redv + DIM * 16;       // [128 r][16 tx]

    const int tid = threadIdx.x;
    const int tx = tid & 15, ty = tid >> 4;
    const size_t row0 = (size_t)blockIdx.x * DIM;

    // Load A and X tile (both as float4, X transposed on store)
    const float4* Xg4 = (const float4*)(X + row0 * DIM);
    const float4* Ag4 = (const float4*)g_A;
    #pragma unroll
    for (int it = 0; it < 16; it++) {
        const int i = it * 256 + tid;            // float4 index, 0..4095
        const int r = i >> 5;
        const int c = (i & 31) * 4;
        const float4 av = Ag4[i];
        *(float4*)&As[r * PAD + c] = av;
        const float4 xv = Xg4[i];
        XsT[(c + 0) * PAD + r] = xv.x;
        XsT[(c + 1) * PAD + r] = xv.y;
        XsT[(c + 2) * PAD + r] = xv.z;
        XsT[(c + 3) * PAD + r] = xv.w;
    }
    __syncthreads();

    const int r0 = ty * 8;   // this thread's 8 rows (4 packed pairs)
    const int c0 = tx * 8;   // this thread's 8 output columns

    u64 acc[4][8];
    #pragma unroll
    for (int p = 0; p < 4; p++)
        #pragma unroll
        for (int q = 0; q < 8; q++) acc[p][q] = 0ull;

    #pragma unroll 2
    for (int k = 0; k < DIM; k++) {
        u64 a2[4];
        const u64* ap = (const u64*)&XsT[k * PAD + r0];
        #pragma unroll
        for (int p = 0; p < 4; p++) a2[p] = ap[p];
        const float4 b0 = *(const float4*)&As[k * PAD + c0];
        const float4 b1 = *(const float4*)&As[k * PAD + c0 + 4];
        u64 b2[8];
        b2[0] = dup2(b0.x); b2[1] = dup2(b0.y); b2[2] = dup2(b0.z); b2[3] = dup2(b0.w);
        b2[4] = dup2(b1.x); b2[5] = dup2(b1.y); b2[6] = dup2(b1.z); b2[7] = dup2(b1.w);
        #pragma unroll
        for (int p = 0; p < 4; p++)
            #pragma unroll
            for (int q = 0; q < 8; q++)
                acc[p][q] = ffma2(a2[p], b2[q], acc[p][q]);
    }

    // Epilogue: partial x.y and x.x over this thread's 8 columns
    u64 v2[4] = {0ull, 0ull, 0ull, 0ull};
    u64 n2[4] = {0ull, 0ull, 0ull, 0ull};
    #pragma unroll
    for (int q = 0; q < 8; q++) {
        const u64* xp = (const u64*)&XsT[(c0 + q) * PAD + r0];
        #pragma unroll
        for (int p = 0; p < 4; p++) {
            const u64 x2 = xp[p];
            v2[p] = ffma2(x2, acc[p][q], v2[p]);
            n2[p] = ffma2(x2, x2, n2[p]);
        }
    }
    #pragma unroll
    for (int p = 0; p < 4; p++) {
        const float2 fv = *(const float2*)&v2[p];
        const float2 fn = *(const float2*)&n2[p];
        redv[(r0 + 2 * p + 0) * 16 + tx] = fv.x;
        redv[(r0 + 2 * p + 1) * 16 + tx] = fv.y;
        redn[(r0 + 2 * p + 0) * 16 + tx] = fn.x;
        redn[(r0 + 2 * p + 1) * 16 + tx] = fn.y;
    }
    __syncthreads();

    if (tid < DIM) {
        float sv = 0.0f, sn = 0.0f;
        #pragma unroll
        for (int i = 0; i < 16; i++) {
            sv += redv[tid * 16 + i];
            sn += redn[tid * 16 + i];
        }
        out[row0 + tid] = sv / sn;
    }
}

// ---------------------------------------------------------------------------
extern "C" void kernel_launch(void* const* d_in, const int* in_sizes, int n_in,
                              void* d_out, int out_size) {
    const float* x = (const float*)d_in[0];
    const float* w = (const float*)d_in[1];
    if (n_in >= 2 && in_sizes[0] == NLAYERS * 7 * 3) {  // robust to input order
        x = (const float*)d_in[1];
        w = (const float*)d_in[0];
    }
    const int batch = (in_sizes[0] == NLAYERS * 7 * 3) ? in_sizes[1] / DIM
                                                       : in_sizes[0] / DIM;

    const int smem_bytes = (2 * DIM * PAD + 2 * DIM * 16) * (int)sizeof(float);
    cudaFuncSetAttribute(vqa_main_kernel,
                         cudaFuncAttributeMaxDynamicSharedMemorySize, smem_bytes);

    build_u_kernel<<<DIM, DIM>>>(w);
    build_a_kernel<<<DIM, DIM>>>();
    vqa_main_kernel<<<batch / DIM, 256, smem_bytes>>>(x, (float*)d_out);
}

// round 4
// speedup vs baseline: 4.0344x; 4.0344x over previous
#include <cuda_runtime.h>
#include <cuda_fp16.h>
#include <cstdint>

#define DIM 128
#define NL 4

// ---------------------------------------------------------------------------
// Device scratch (no allocations allowed)
// ---------------------------------------------------------------------------
__device__ float g_Ur[DIM * DIM];
__device__ float g_Ui[DIM * DIM];
// Pre-swizzled fp16 smem image of B^T = [Ahi | Alo] stacked along k.
// Layout: [n=128 rows][k=256 cols], row pitch 512 B, 16B-chunk XOR swizzle.
__device__ __align__(16) unsigned char g_Aimg[DIM * 2 * DIM * 2];  // 64 KB

// ---------------------------------------------------------------------------
// Helpers
// ---------------------------------------------------------------------------
__device__ __forceinline__ uint32_t smem_u32(const void* p) {
    uint32_t a;
    asm("{ .reg .u64 t; cvta.to.shared.u64 t, %1; cvt.u32.u64 %0, t; }"
        : "=r"(a) : "l"(p));
    return a;
}

__device__ __forceinline__ void ldsm_x4(uint32_t* r, uint32_t addr) {
    asm volatile("ldmatrix.sync.aligned.m8n8.x4.shared.b16 {%0,%1,%2,%3}, [%4];"
                 : "=r"(r[0]), "=r"(r[1]), "=r"(r[2]), "=r"(r[3]) : "r"(addr));
}
__device__ __forceinline__ void ldsm_x2(uint32_t* r, uint32_t addr) {
    asm volatile("ldmatrix.sync.aligned.m8n8.x2.shared.b16 {%0,%1}, [%2];"
                 : "=r"(r[0]), "=r"(r[1]) : "r"(addr));
}
__device__ __forceinline__ void mma16816(float* d, const uint32_t* a,
                                         const uint32_t* b) {
    asm volatile(
        "mma.sync.aligned.m16n8k16.row.col.f32.f16.f16.f32 "
        "{%0,%1,%2,%3}, {%4,%5,%6,%7}, {%8,%9}, {%0,%1,%2,%3};"
        : "+f"(d[0]), "+f"(d[1]), "+f"(d[2]), "+f"(d[3])
        : "r"(a[0]), "r"(a[1]), "r"(a[2]), "r"(a[3]), "r"(b[0]), "r"(b[1]));
}

// ---------------------------------------------------------------------------
// Prep 1: build U columns (fp32 circuit simulation; 128 blocks x 128 thr)
// qubit w <-> bit (6-w) of the linear index.  (Validated in R2.)
// ---------------------------------------------------------------------------
__global__ void build_u_kernel(const float* __restrict__ w) {
    __shared__ float sr[DIM], si[DIM];
    __shared__ float gc[28][8];
    const int t = threadIdx.x;
    const int j = blockIdx.x;
    if (t < 28) {
        const float phi = w[t * 3 + 0], th = w[t * 3 + 1], om = w[t * 3 + 2];
        float s, c;   sincosf(0.5f * th, &s, &c);
        float sa, ca; sincosf(0.5f * (phi + om), &sa, &ca);
        float sb, cb; sincosf(0.5f * (phi - om), &sb, &cb);
        gc[t][0] =  ca * c; gc[t][1] = -sa * c;   // u00
        gc[t][2] = -cb * s; gc[t][3] = -sb * s;   // u01
        gc[t][4] =  cb * s; gc[t][5] = -sb * s;   // u10
        gc[t][6] =  ca * c; gc[t][7] =  sa * c;   // u11
    }
    sr[t] = (t == j) ? 1.0f : 0.0f;
    si[t] = 0.0f;
    __syncthreads();

    for (int l = 0; l < NL; l++) {
        for (int q = 0; q < 7; q++) {
            const int g = l * 7 + q;
            const int bit = 1 << (6 - q);
            if (!(t & bit)) {
                const int i1 = t | bit;
                const float a0r = sr[t],  a0i = si[t];
                const float a1r = sr[i1], a1i = si[i1];
                sr[t]  = gc[g][0] * a0r - gc[g][1] * a0i + gc[g][2] * a1r - gc[g][3] * a1i;
                si[t]  = gc[g][0] * a0i + gc[g][1] * a0r + gc[g][2] * a1i + gc[g][3] * a1r;
                sr[i1] = gc[g][4] * a0r - gc[g][5] * a0i + gc[g][6] * a1r - gc[g][7] * a1i;
                si[i1] = gc[g][4] * a0i + gc[g][5] * a0r + gc[g][6] * a1i + gc[g][7] * a1r;
            }
            __syncthreads();
        }
        // fused CNOT layer: new[t] = old[m0(m1(...m6(t)))]
        const int r = (l % 6) + 1;
        int s = t;
        #pragma unroll
        for (int q = 6; q >= 0; q--) {
            const int cb = 1 << (6 - q);
            const int tb = 1 << (6 - ((q + r) % 7));
            if (s & cb) s ^= tb;
        }
        const float ar = sr[s], ai = si[s];
        __syncthreads();
        sr[t] = ar; si[t] = ai;
        __syncthreads();
    }
    g_Ur[t * DIM + j] = sr[t];
    g_Ui[t * DIM + j] = si[t];
}

// ---------------------------------------------------------------------------
// Prep 2: A[i][j] = sum_k sgn(k)(Ur[k][i]Ur[k][j]+Ui[k][i]Ui[k][j]);
// written as the swizzled fp16 hi/lo B^T image (A symmetric).
// ---------------------------------------------------------------------------
__global__ void build_a_kernel() {
    __shared__ float cr[DIM], ci[DIM];
    const int i = blockIdx.x;
    const int j = threadIdx.x;
    const float sg = (__popc(j & 0x41) & 1) ? -1.0f : 1.0f;
    cr[j] = sg * g_Ur[j * DIM + i];
    ci[j] = sg * g_Ui[j * DIM + i];
    __syncthreads();
    float acc = 0.0f;
    #pragma unroll 8
    for (int k = 0; k < DIM; k++)
        acc += cr[k] * g_Ur[k * DIM + j] + ci[k] * g_Ui[k * DIM + j];
    const __half hi = __float2half_rn(acc);
    const __half lo = __float2half_rn(acc - __half2float(hi));
    // image[n=i][k=j] = Ahi[i][j]; image[n=i][k=j+128] = Alo[i][j]
    const int chi = (j >> 3), clo = chi + 16, sel = i & 7, within = (j & 7) * 2;
    *(__half*)(g_Aimg + i * 512 + ((chi ^ sel) << 4) + within) = hi;
    *(__half*)(g_Aimg + i * 512 + ((clo ^ sel) << 4) + within) = lo;
}

// ---------------------------------------------------------------------------
// Main kernel: CTA = 128 threads / 128 batch rows; warp owns 32 rows.
// smem: As image 64KB @0, Xs fp16 32KB @65536, norms @98304.
// ---------------------------------------------------------------------------
#define AS_OFF   0
#define XS_OFF   65536
#define NORM_OFF 98304
#define SMEM_BYTES 98816

__global__ __launch_bounds__(128)
void vqa_main(const float* __restrict__ X, float* __restrict__ out) {
    extern __shared__ __align__(16) unsigned char smem[];
    const uint32_t sb = smem_u32(smem);
    const int tid = threadIdx.x;
    const int w = tid >> 5, L = tid & 31;
    const size_t row0 = (size_t)blockIdx.x * DIM;

    // ---- copy pre-swizzled A image (64KB) ----
    {
        const uint4* Ag = (const uint4*)g_Aimg;
        uint4* Asv = (uint4*)(smem + AS_OFF);
        #pragma unroll
        for (int i = 0; i < 32; i++) Asv[i * 128 + tid] = Ag[i * 128 + tid];
    }

    // ---- load X, convert fp16 (swizzled), per-row fp32 norms ----
    {
        float* norms = (float*)(smem + NORM_OFF);
        const float4* Xg = (const float4*)(X + row0 * DIM);
        #pragma unroll
        for (int i = 0; i < 32; i++) {
            const float4 v = Xg[i * 128 + tid];
            const int row = i * 4 + w;       // warp-uniform row
            const int c4 = L;                // float4 index within row
            const __half2 h01 = __floats2half2_rn(v.x, v.y);
            const __half2 h23 = __floats2half2_rn(v.z, v.w);
            struct __align__(8) H4 { __half2 a, b; };
            const int byte = XS_OFF + row * 256 +
                             (((c4 >> 1) ^ (row & 7)) << 4) + ((c4 & 1) << 3);
            *(H4*)(smem + byte) = H4{h01, h23};
            float p = v.x * v.x + v.y * v.y + v.z * v.z + v.w * v.w;
            #pragma unroll
            for (int o = 16; o > 0; o >>= 1)
                p += __shfl_xor_sync(0xffffffffu, p, o);
            if (L == 0) norms[row] = p;
        }
    }
    __syncthreads();

    // ---- GEMM: D[32 x 128] += Xs[32 x 128] * (Ahi + Alo stacked, K=256) ----
    float d[16][2][4];
    #pragma unroll
    for (int n = 0; n < 16; n++)
        #pragma unroll
        for (int m = 0; m < 2; m++)
            #pragma unroll
            for (int e = 0; e < 4; e++) d[n][m][e] = 0.0f;

    const int m0 = w * 32;
    const int ra0 = m0 + (L & 15);         // a-frag row, m-tile 0
    const int ra1 = ra0 + 16;              // m-tile 1
    const int bn = L & 7;                  // b-frag n-row within tile
    const int bh = (L >> 3) & 1;           // b-frag k-chunk half

    #pragma unroll 1
    for (int k = 0; k < 8; k++) {          // k-step = 16 cols of X
        uint32_t a0[4], a1[4];
        const int ach = 2 * k + (L >> 4);
        ldsm_x4(a0, sb + XS_OFF + ra0 * 256 + ((ach ^ (ra0 & 7)) << 4));
        ldsm_x4(a1, sb + XS_OFF + ra1 * 256 + ((ach ^ (ra1 & 7)) << 4));
        const int bch_hi = 2 * k + bh;
        const int bch_lo = bch_hi + 16;
        #pragma unroll
        for (int n = 0; n < 16; n++) {
            const int nr = n * 8 + bn;
            const uint32_t brow = sb + AS_OFF + nr * 512;
            const int sel = nr & 7;
            uint32_t b[2];
            ldsm_x2(b, brow + ((bch_hi ^ sel) << 4));
            mma16816(d[n][0], a0, b);
            mma16816(d[n][1], a1, b);
            ldsm_x2(b, brow + ((bch_lo ^ sel) << 4));
            mma16816(d[n][0], a0, b);
            mma16816(d[n][1], a1, b);
        }
    }

    // ---- epilogue: out[row] = dot(x_tilde[row], Y[row]) / norm[row] ----
    const int q = L & 3, rq = L >> 2;
    const float* norms = (const float*)(smem + NORM_OFF);
    float acc[4] = {0.f, 0.f, 0.f, 0.f};
    int rows[4];
    #pragma unroll
    for (int h = 0; h < 4; h++) rows[h] = m0 + (h >> 1) * 16 + (h & 1) * 8 + rq;

    #pragma unroll
    for (int n = 0; n < 16; n++) {
        #pragma unroll
        for (int h = 0; h < 4; h++) {
            const int row = rows[h];
            const int byte = XS_OFF + row * 256 + ((n ^ (row & 7)) << 4) + (q << 2);
            const float2 xf = __half22float2(*(const __half2*)(smem + byte));
            const int mt = h >> 1, pr = (h & 1) * 2;
            acc[h] += xf.x * d[n][mt][pr] + xf.y * d[n][mt][pr + 1];
        }
    }
    #pragma unroll
    for (int h = 0; h < 4; h++) {
        acc[h] += __shfl_xor_sync(0xffffffffu, acc[h], 1);
        acc[h] += __shfl_xor_sync(0xffffffffu, acc[h], 2);
    }
    if (q == 0) {
        #pragma unroll
        for (int h = 0; h < 4; h++)
            out[row0 + rows[h]] = acc[h] / norms[rows[h]];
    }
}

// ---------------------------------------------------------------------------
extern "C" void kernel_launch(void* const* d_in, const int* in_sizes, int n_in,
                              void* d_out, int out_size) {
    const float* x = (const float*)d_in[0];
    const float* w = (const float*)d_in[1];
    int xi = 0;
    if (n_in >= 2 && in_sizes[0] == NL * 7 * 3) {
        x = (const float*)d_in[1];
        w = (const float*)d_in[0];
        xi = 1;
    }
    const int batch = in_sizes[xi] / DIM;

    cudaFuncSetAttribute(vqa_main, cudaFuncAttributeMaxDynamicSharedMemorySize,
                         SMEM_BYTES);

    build_u_kernel<<<DIM, DIM>>>(w);
    build_a_kernel<<<DIM, DIM>>>();
    vqa_main<<<batch / DIM, 128, SMEM_BYTES>>>(x, (float*)d_out);
}

// round 5
// speedup vs baseline: 4.6419x; 1.1506x over previous
#include <cuda_runtime.h>
#include <cuda_fp16.h>
#include <cstdint>

#define DIM 128
#define NL 4

// ---------------------------------------------------------------------------
// Device scratch (no allocations allowed)
// ---------------------------------------------------------------------------
__device__ float g_Ur[DIM * DIM];    // U[t][j]
__device__ float g_Ui[DIM * DIM];
__device__ float g_UrT[DIM * DIM];   // U^T[j][t]
__device__ float g_UiT[DIM * DIM];
// Pre-swizzled fp16 smem image of A (B^T operand), [n=128][k=128], 256B pitch.
__device__ __align__(16) unsigned char g_Aimg[DIM * DIM * 2];  // 32 KB

// ---------------------------------------------------------------------------
// Helpers
// ---------------------------------------------------------------------------
__device__ __forceinline__ uint32_t smem_u32(const void* p) {
    uint32_t a;
    asm("{ .reg .u64 t; cvta.to.shared.u64 t, %1; cvt.u32.u64 %0, t; }"
        : "=r"(a) : "l"(p));
    return a;
}
__device__ __forceinline__ void ldsm_x4(uint32_t* r, uint32_t addr) {
    asm volatile("ldmatrix.sync.aligned.m8n8.x4.shared.b16 {%0,%1,%2,%3}, [%4];"
                 : "=r"(r[0]), "=r"(r[1]), "=r"(r[2]), "=r"(r[3]) : "r"(addr));
}
__device__ __forceinline__ void mma16816(float* d, const uint32_t* a,
                                         const uint32_t* b) {
    asm volatile(
        "mma.sync.aligned.m16n8k16.row.col.f32.f16.f16.f32 "
        "{%0,%1,%2,%3}, {%4,%5,%6,%7}, {%8,%9}, {%0,%1,%2,%3};"
        : "+f"(d[0]), "+f"(d[1]), "+f"(d[2]), "+f"(d[3])
        : "r"(a[0]), "r"(a[1]), "r"(a[2]), "r"(a[3]), "r"(b[0]), "r"(b[1]));
}

// ---------------------------------------------------------------------------
// Prep 1: build U columns.  ONE WARP per column (grid=128, block=32):
// stage chain is __syncwarp-based (~23cyc) instead of 4-warp BAR (~390cyc).
// qubit w <-> bit (6-w) of the linear index.
// ---------------------------------------------------------------------------
__global__ __launch_bounds__(32)
void build_u_kernel(const float* __restrict__ w) {
    __shared__ float sr[DIM], si[DIM];
    __shared__ float gc[28][8];
    const int L = threadIdx.x;
    const int j = blockIdx.x;

    if (L < 28) {
        const float phi = w[L * 3 + 0], th = w[L * 3 + 1], om = w[L * 3 + 2];
        float s, c;   sincosf(0.5f * th, &s, &c);
        float sa, ca; sincosf(0.5f * (phi + om), &sa, &ca);
        float sb, cb; sincosf(0.5f * (phi - om), &sb, &cb);
        gc[L][0] =  ca * c; gc[L][1] = -sa * c;   // u00
        gc[L][2] = -cb * s; gc[L][3] = -sb * s;   // u01
        gc[L][4] =  cb * s; gc[L][5] = -sb * s;   // u10
        gc[L][6] =  ca * c; gc[L][7] =  sa * c;   // u11
    }
    #pragma unroll
    for (int m = 0; m < 4; m++) {
        const int t = L + 32 * m;
        sr[t] = (t == j) ? 1.0f : 0.0f;
        si[t] = 0.0f;
    }
    __syncwarp();

    for (int l = 0; l < NL; l++) {
        for (int q = 0; q < 7; q++) {
            const int g = l * 7 + q;
            const int B = 1 << (6 - q);
            const float u00r = gc[g][0], u00i = gc[g][1];
            const float u01r = gc[g][2], u01i = gc[g][3];
            const float u10r = gc[g][4], u10i = gc[g][5];
            const float u11r = gc[g][6], u11i = gc[g][7];
            #pragma unroll
            for (int h = 0; h < 2; h++) {
                const int p = L + 32 * h;                       // pair 0..63
                const int i0 = ((p & ~(B - 1)) << 1) | (p & (B - 1));
                const int i1 = i0 | B;
                const float a0r = sr[i0], a0i = si[i0];
                const float a1r = sr[i1], a1i = si[i1];
                sr[i0] = u00r * a0r - u00i * a0i + u01r * a1r - u01i * a1i;
                si[i0] = u00r * a0i + u00i * a0r + u01r * a1i + u01i * a1r;
                sr[i1] = u10r * a0r - u10i * a0i + u11r * a1r - u11i * a1i;
                si[i1] = u10r * a0i + u10i * a0r + u11r * a1i + u11i * a1r;
            }
            __syncwarp();
        }
        // fused CNOT layer: new[t] = old[s(t)]
        const int r = (l % 6) + 1;
        float ar[4], ai[4];
        #pragma unroll
        for (int m = 0; m < 4; m++) {
            int s = L + 32 * m;
            #pragma unroll
            for (int q = 6; q >= 0; q--) {
                const int cb = 1 << (6 - q);
                const int tb = 1 << (6 - ((q + r) % 7));
                if (s & cb) s ^= tb;
            }
            ar[m] = sr[s]; ai[m] = si[s];
        }
        __syncwarp();
        #pragma unroll
        for (int m = 0; m < 4; m++) {
            sr[L + 32 * m] = ar[m]; si[L + 32 * m] = ai[m];
        }
        __syncwarp();
    }
    #pragma unroll
    for (int m = 0; m < 4; m++) {
        const int t = L + 32 * m;
        g_Ur[t * DIM + j] = sr[t];
        g_Ui[t * DIM + j] = si[t];
        g_UrT[j * DIM + t] = sr[t];   // coalesced
        g_UiT[j * DIM + t] = si[t];
    }
}

// ---------------------------------------------------------------------------
// Prep 2: A[i][j] = sum_k sgn(k)(Ur[k][i]Ur[k][j]+Ui[k][i]Ui[k][j]);
// written as the swizzled fp16 B^T image (A symmetric -> row i).
// ---------------------------------------------------------------------------
__global__ void build_a_kernel() {
    __shared__ float cr[DIM], ci[DIM];
    const int i = blockIdx.x;
    const int j = threadIdx.x;
    const float sg = (__popc(j & 0x41) & 1) ? -1.0f : 1.0f;
    cr[j] = sg * g_UrT[i * DIM + j];     // = sgn(j) * Ur[j][i], coalesced
    ci[j] = sg * g_UiT[i * DIM + j];
    __syncthreads();
    float acc = 0.0f;
    #pragma unroll 8
    for (int k = 0; k < DIM; k++)
        acc += cr[k] * g_Ur[k * DIM + j] + ci[k] * g_Ui[k * DIM + j];
    const __half hi = __float2half_rn(acc);
    const int chi = j >> 3, sel = i & 7, within = (j & 7) * 2;
    *(__half*)(g_Aimg + i * 256 + ((chi ^ sel) << 4) + within) = hi;
}

// ---------------------------------------------------------------------------
// Main kernel: CTA = 128 threads / 128 batch rows; warp owns M=32, N=128,
// K=128 (hi only).  smem: A 32KB @0, Xs fp16 32KB @32768, norms @65536.
// ---------------------------------------------------------------------------
#define AS_OFF   0
#define XS_OFF   32768
#define NORM_OFF 65536
#define SMEM_BYTES 66048

__global__ __launch_bounds__(128)
void vqa_main(const float* __restrict__ X, float* __restrict__ out) {
    extern __shared__ __align__(16) unsigned char smem[];
    const uint32_t sb = smem_u32(smem);
    const int tid = threadIdx.x;
    const int w = tid >> 5, L = tid & 31;
    const size_t row0 = (size_t)blockIdx.x * DIM;

    // ---- copy pre-swizzled A image (32KB) ----
    {
        const uint4* Ag = (const uint4*)g_Aimg;
        uint4* Asv = (uint4*)(smem + AS_OFF);
        #pragma unroll
        for (int i = 0; i < 16; i++) Asv[i * 128 + tid] = Ag[i * 128 + tid];
    }

    // ---- load X, convert fp16 (swizzled), per-row fp32 norms ----
    {
        float* norms = (float*)(smem + NORM_OFF);
        const float4* Xg = (const float4*)(X + row0 * DIM);
        #pragma unroll
        for (int i = 0; i < 32; i++) {
            const float4 v = Xg[i * 128 + tid];
            const int row = i * 4 + w;       // warp-uniform row
            const int c4 = L;                // float4 index within row (0..31)
            const __half2 h01 = __floats2half2_rn(v.x, v.y);
            const __half2 h23 = __floats2half2_rn(v.z, v.w);
            struct __align__(8) H4 { __half2 a, b; };
            const int byte = XS_OFF + row * 256 +
                             (((c4 >> 1) ^ (row & 7)) << 4) + ((c4 & 1) << 3);
            *(H4*)(smem + byte) = H4{h01, h23};
            float p = v.x * v.x + v.y * v.y + v.z * v.z + v.w * v.w;
            #pragma unroll
            for (int o = 16; o > 0; o >>= 1)
                p += __shfl_xor_sync(0xffffffffu, p, o);
            if (L == 0) norms[row] = p;
        }
    }
    __syncthreads();

    // ---- GEMM: D[32 x 128] = Xs[32 x 128k] * A^T  (K=128) ----
    float d[16][2][4];
    #pragma unroll
    for (int n = 0; n < 16; n++)
        #pragma unroll
        for (int m = 0; m < 2; m++)
            #pragma unroll
            for (int e = 0; e < 4; e++) d[n][m][e] = 0.0f;

    const int m0 = w * 32;
    const int ra0 = m0 + (L & 15);          // a-frag rows, m-tile 0
    const int ra1 = ra0 + 16;               // m-tile 1
    // B ldsm_x4 lane mapping: covers two n-tiles (n16) x k16
    const int bnr = ((L >> 4) << 3) + (L & 7);   // n-row within n16 group
    const int bh = (L >> 3) & 1;                 // k8 half

    #pragma unroll 1
    for (int k = 0; k < 8; k++) {           // k-step = 16 halves
        uint32_t a0[4], a1[4];
        const int ach = 2 * k + (L >> 4);
        ldsm_x4(a0, sb + XS_OFF + ra0 * 256 + ((ach ^ (ra0 & 7)) << 4));
        ldsm_x4(a1, sb + XS_OFF + ra1 * 256 + ((ach ^ (ra1 & 7)) << 4));
        const int bch = 2 * k + bh;
        #pragma unroll
        for (int n2 = 0; n2 < 8; n2++) {
            const int nr = n2 * 16 + bnr;
            uint32_t b[4];
            ldsm_x4(b, sb + AS_OFF + nr * 256 + ((bch ^ (nr & 7)) << 4));
            mma16816(d[2 * n2][0],     a0, b);
            mma16816(d[2 * n2][1],     a1, b);
            mma16816(d[2 * n2 + 1][0], a0, b + 2);
            mma16816(d[2 * n2 + 1][1], a1, b + 2);
        }
    }

    // ---- epilogue: out[row] = dot(x_tilde[row], Y[row]) / norm[row] ----
    const int q = L & 3, rq = L >> 2;
    const float* norms = (const float*)(smem + NORM_OFF);
    float acc[4] = {0.f, 0.f, 0.f, 0.f};
    int rows[4];
    #pragma unroll
    for (int h = 0; h < 4; h++) rows[h] = m0 + (h >> 1) * 16 + (h & 1) * 8 + rq;

    #pragma unroll
    for (int n = 0; n < 16; n++) {
        #pragma unroll
        for (int h = 0; h < 4; h++) {
            const int row = rows[h];
            const int byte = XS_OFF + row * 256 + ((n ^ (row & 7)) << 4) + (q << 2);
            const float2 xf = __half22float2(*(const __half2*)(smem + byte));
            const int mt = h >> 1, pr = (h & 1) * 2;
            acc[h] += xf.x * d[n][mt][pr] + xf.y * d[n][mt][pr + 1];
        }
    }
    #pragma unroll
    for (int h = 0; h < 4; h++) {
        acc[h] += __shfl_xor_sync(0xffffffffu, acc[h], 1);
        acc[h] += __shfl_xor_sync(0xffffffffu, acc[h], 2);
    }
    if (q == 0) {
        #pragma unroll
        for (int h = 0; h < 4; h++)
            out[row0 + rows[h]] = acc[h] / norms[rows[h]];
    }
}

// ---------------------------------------------------------------------------
extern "C" void kernel_launch(void* const* d_in, const int* in_sizes, int n_in,
                              void* d_out, int out_size) {
    const float* x = (const float*)d_in[0];
    const float* w = (const float*)d_in[1];
    int xi = 0;
    if (n_in >= 2 && in_sizes[0] == NL * 7 * 3) {
        x = (const float*)d_in[1];
        w = (const float*)d_in[0];
        xi = 1;
    }
    const int batch = in_sizes[xi] / DIM;

    cudaFuncSetAttribute(vqa_main, cudaFuncAttributeMaxDynamicSharedMemorySize,
                         SMEM_BYTES);

    build_u_kernel<<<DIM, 32>>>(w);
    build_a_kernel<<<DIM, DIM>>>();
    vqa_main<<<batch / DIM, 128, SMEM_BYTES>>>(x, (float*)d_out);
}

// round 6
// speedup vs baseline: 5.2992x; 1.1416x over previous
#include <cuda_runtime.h>
#include <cuda_fp16.h>
#include <cstdint>

#define DIM 128
#define NL 4

// ---------------------------------------------------------------------------
// Device scratch (no allocations allowed)
// ---------------------------------------------------------------------------
__device__ float g_Ur[DIM * DIM];    // U[t][j]   (row t, col j)
__device__ float g_Ui[DIM * DIM];
__device__ float g_UrT[DIM * DIM];   // U^T[j][t]
__device__ float g_UiT[DIM * DIM];
// Pre-swizzled fp16 smem image of A (B^T operand), [n=128][k=128], 256B pitch.
__device__ __align__(16) unsigned char g_Aimg[DIM * DIM * 2];  // 32 KB

// ---------------------------------------------------------------------------
// Helpers
// ---------------------------------------------------------------------------
__device__ __forceinline__ uint32_t smem_u32(const void* p) {
    uint32_t a;
    asm("{ .reg .u64 t; cvta.to.shared.u64 t, %1; cvt.u32.u64 %0, t; }"
        : "=r"(a) : "l"(p));
    return a;
}
__device__ __forceinline__ void ldsm_x4(uint32_t* r, uint32_t addr) {
    asm volatile("ldmatrix.sync.aligned.m8n8.x4.shared.b16 {%0,%1,%2,%3}, [%4];"
                 : "=r"(r[0]), "=r"(r[1]), "=r"(r[2]), "=r"(r[3]) : "r"(addr));
}
__device__ __forceinline__ void mma16816(float* d, const uint32_t* a,
                                         const uint32_t* b) {
    asm volatile(
        "mma.sync.aligned.m16n8k16.row.col.f32.f16.f16.f32 "
        "{%0,%1,%2,%3}, {%4,%5,%6,%7}, {%8,%9}, {%0,%1,%2,%3};"
        : "+f"(d[0]), "+f"(d[1]), "+f"(d[2]), "+f"(d[3])
        : "r"(a[0]), "r"(a[1]), "r"(a[2]), "r"(a[3]), "r"(b[0]), "r"(b[1]));
}

// ---------------------------------------------------------------------------
// Prep 1: build U columns.  One warp per column; state lives in REGISTERS
// (4 complex amps / thread, t = (m<<5)|L).  Qubit bits <=4 are shfl_xor
// butterflies; bits 5,6 are in-register pair ops.  CNOT = shfl gather.
// qubit w <-> bit (6-w) of the linear index.
// ---------------------------------------------------------------------------
__global__ __launch_bounds__(32)
void build_u_kernel(const float* __restrict__ w) {
    __shared__ float gc[28][8];
    const int L = threadIdx.x;
    const int j = blockIdx.x;
    const unsigned FULL = 0xffffffffu;

    if (L < 28) {
        const float phi = w[L * 3 + 0], th = w[L * 3 + 1], om = w[L * 3 + 2];
        float s, c;   sincosf(0.5f * th, &s, &c);
        float sa, ca; sincosf(0.5f * (phi + om), &sa, &ca);
        float sb, cb; sincosf(0.5f * (phi - om), &sb, &cb);
        gc[L][0] =  ca * c; gc[L][1] = -sa * c;   // u00
        gc[L][2] = -cb * s; gc[L][3] = -sb * s;   // u01
        gc[L][4] =  cb * s; gc[L][5] = -sb * s;   // u10
        gc[L][6] =  ca * c; gc[L][7] =  sa * c;   // u11
    }
    float sr[4], si[4];
    #pragma unroll
    for (int m = 0; m < 4; m++) {
        const int t = (m << 5) | L;
        sr[m] = (t == j) ? 1.0f : 0.0f;
        si[m] = 0.0f;
    }
    __syncwarp();

    #pragma unroll
    for (int l = 0; l < NL; l++) {
        #pragma unroll
        for (int q = 0; q < 7; q++) {
            const int g = l * 7 + q;
            const float u00r = gc[g][0], u00i = gc[g][1];
            const float u01r = gc[g][2], u01i = gc[g][3];
            const float u10r = gc[g][4], u10i = gc[g][5];
            const float u11r = gc[g][6], u11i = gc[g][7];
            const int b = 6 - q;
            if (q >= 2) {
                // lane-bit butterfly via shfl_xor
                const int mask = 1 << b;
                const bool hi = (L & mask) != 0;
                const float c0r = hi ? u10r : u00r, c0i = hi ? u10i : u00i;
                const float c1r = hi ? u11r : u01r, c1i = hi ? u11i : u01i;
                #pragma unroll
                for (int m = 0; m < 4; m++) {
                    const float pr = __shfl_xor_sync(FULL, sr[m], mask);
                    const float pi = __shfl_xor_sync(FULL, si[m], mask);
                    const float a0r = hi ? pr : sr[m], a0i = hi ? pi : si[m];
                    const float a1r = hi ? sr[m] : pr, a1i = hi ? si[m] : pi;
                    sr[m] = c0r * a0r - c0i * a0i + c1r * a1r - c1i * a1i;
                    si[m] = c0r * a0i + c0i * a0r + c1r * a1i + c1i * a1r;
                }
            } else {
                // register-bit gate: q==0 -> m-bit1 (d=2), q==1 -> m-bit0 (d=1)
                const int d = (q == 0) ? 2 : 1;
                #pragma unroll
                for (int m = 0; m < 4; m++) {
                    if (!(m & d)) {
                        const int mh = m | d;
                        const float a0r = sr[m],  a0i = si[m];
                        const float a1r = sr[mh], a1i = si[mh];
                        sr[m]  = u00r * a0r - u00i * a0i + u01r * a1r - u01i * a1i;
                        si[m]  = u00r * a0i + u00i * a0r + u01r * a1i + u01i * a1r;
                        sr[mh] = u10r * a0r - u10i * a0i + u11r * a1r - u11i * a1i;
                        si[mh] = u10r * a0i + u10i * a0r + u11r * a1i + u11i * a1r;
                    }
                }
            }
        }
        // fused CNOT layer: new[t] = old[s(t)]; gather via shfl_idx + select
        const int r = (l % 6) + 1;
        float nr[4], ni[4];
        #pragma unroll
        for (int m = 0; m < 4; m++) {
            int s = (m << 5) | L;
            #pragma unroll
            for (int qq = 6; qq >= 0; qq--) {
                const int cb = 1 << (6 - qq);
                const int tb = 1 << (6 - ((qq + r) % 7));
                if (s & cb) s ^= tb;
            }
            const int Ls = s & 31, ms = s >> 5;
            const float v0r = __shfl_sync(FULL, sr[0], Ls);
            const float v1r = __shfl_sync(FULL, sr[1], Ls);
            const float v2r = __shfl_sync(FULL, sr[2], Ls);
            const float v3r = __shfl_sync(FULL, sr[3], Ls);
            const float v0i = __shfl_sync(FULL, si[0], Ls);
            const float v1i = __shfl_sync(FULL, si[1], Ls);
            const float v2i = __shfl_sync(FULL, si[2], Ls);
            const float v3i = __shfl_sync(FULL, si[3], Ls);
            nr[m] = (ms == 0) ? v0r : (ms == 1) ? v1r : (ms == 2) ? v2r : v3r;
            ni[m] = (ms == 0) ? v0i : (ms == 1) ? v1i : (ms == 2) ? v2i : v3i;
        }
        #pragma unroll
        for (int m = 0; m < 4; m++) { sr[m] = nr[m]; si[m] = ni[m]; }
    }
    #pragma unroll
    for (int m = 0; m < 4; m++) {
        const int t = (m << 5) | L;
        g_Ur[t * DIM + j]  = sr[m];
        g_Ui[t * DIM + j]  = si[m];
        g_UrT[j * DIM + t] = sr[m];   // coalesced
        g_UiT[j * DIM + t] = si[m];
    }
}

// ---------------------------------------------------------------------------
// Prep 2: A[i][j] = sum_k sgn(k)(Ur[k][i]Ur[k][j]+Ui[k][i]Ui[k][j]);
// written as the swizzled fp16 B^T image (A symmetric -> row i).
// ---------------------------------------------------------------------------
__global__ void build_a_kernel() {
    __shared__ float cr[DIM], ci[DIM];
    const int i = blockIdx.x;
    const int j = threadIdx.x;
    const float sg = (__popc(j & 0x41) & 1) ? -1.0f : 1.0f;
    cr[j] = sg * g_UrT[i * DIM + j];     // = sgn(j) * Ur[j][i], coalesced
    ci[j] = sg * g_UiT[i * DIM + j];
    __syncthreads();
    float acc = 0.0f;
    #pragma unroll 8
    for (int k = 0; k < DIM; k++)
        acc += cr[k] * g_Ur[k * DIM + j] + ci[k] * g_Ui[k * DIM + j];
    const __half hi = __float2half_rn(acc);
    const int chi = j >> 3, sel = i & 7, within = (j & 7) * 2;
    *(__half*)(g_Aimg + i * 256 + ((chi ^ sel) << 4) + within) = hi;
}

// ---------------------------------------------------------------------------
// Main kernel: CTA = 256 threads (8 warps) / 128 batch rows.
// Warp (wm, wn): M=32 rows (wm*32), N=64 cols (wn*64), K=128.
// smem: A 32KB @0, Xs fp16 32KB @32768, norms @65536, partials @66048.
// ---------------------------------------------------------------------------
#define AS_OFF   0
#define XS_OFF   32768
#define NORM_OFF 65536
#define PART_OFF 66048
#define SMEM_BYTES 67072

__global__ __launch_bounds__(256, 2)
void vqa_main(const float* __restrict__ X, float* __restrict__ out) {
    extern __shared__ __align__(16) unsigned char smem[];
    const uint32_t sb = smem_u32(smem);
    const int tid = threadIdx.x;
    const int w = tid >> 5, L = tid & 31;
    const int wm = w & 3, wn = w >> 2;
    const size_t row0 = (size_t)blockIdx.x * DIM;

    // ---- copy pre-swizzled A image (32KB) ----
    {
        const uint4* Ag = (const uint4*)g_Aimg;
        uint4* Asv = (uint4*)(smem + AS_OFF);
        #pragma unroll
        for (int i = 0; i < 8; i++) Asv[i * 256 + tid] = Ag[i * 256 + tid];
    }

    // ---- load X, convert fp16 (swizzled), per-row fp32 norms ----
    {
        float* norms = (float*)(smem + NORM_OFF);
        const float4* Xg = (const float4*)(X + row0 * DIM);
        #pragma unroll
        for (int i = 0; i < 16; i++) {
            const float4 v = Xg[i * 256 + tid];
            const int row = i * 8 + w;       // warp-uniform row
            const int c4 = L;                // float4 index within row (0..31)
            const __half2 h01 = __floats2half2_rn(v.x, v.y);
            const __half2 h23 = __floats2half2_rn(v.z, v.w);
            struct __align__(8) H4 { __half2 a, b; };
            const int byte = XS_OFF + row * 256 +
                             (((c4 >> 1) ^ (row & 7)) << 4) + ((c4 & 1) << 3);
            *(H4*)(smem + byte) = H4{h01, h23};
            float p = v.x * v.x + v.y * v.y + v.z * v.z + v.w * v.w;
            #pragma unroll
            for (int o = 16; o > 0; o >>= 1)
                p += __shfl_xor_sync(0xffffffffu, p, o);
            if (L == 0) norms[row] = p;
        }
    }
    __syncthreads();

    // ---- GEMM: warp computes D[32 x 64] over K=128 ----
    float d[8][2][4];
    #pragma unroll
    for (int n = 0; n < 8; n++)
        #pragma unroll
        for (int m = 0; m < 2; m++)
            #pragma unroll
            for (int e = 0; e < 4; e++) d[n][m][e] = 0.0f;

    const int m0 = wm * 32;
    const int n0 = wn * 64;
    const int ra0 = m0 + (L & 15);          // a-frag rows, m-tile 0
    const int ra1 = ra0 + 16;               // m-tile 1
    // B ldsm_x4 lane mapping: covers two n8-tiles x two k8-halves
    const int bnr = ((L >> 4) << 3) + (L & 7);
    const int bh = (L >> 3) & 1;

    #pragma unroll 2
    for (int k = 0; k < 8; k++) {           // k-step = 16 halves
        uint32_t a0[4], a1[4];
        const int ach = 2 * k + (L >> 4);
        ldsm_x4(a0, sb + XS_OFF + ra0 * 256 + ((ach ^ (ra0 & 7)) << 4));
        ldsm_x4(a1, sb + XS_OFF + ra1 * 256 + ((ach ^ (ra1 & 7)) << 4));
        const int bch = 2 * k + bh;
        #pragma unroll
        for (int n2 = 0; n2 < 4; n2++) {
            const int nr = n0 + n2 * 16 + bnr;
            uint32_t b[4];
            ldsm_x4(b, sb + AS_OFF + nr * 256 + ((bch ^ (nr & 7)) << 4));
            mma16816(d[2 * n2][0],     a0, b);
            mma16816(d[2 * n2][1],     a1, b);
            mma16816(d[2 * n2 + 1][0], a0, b + 2);
            mma16816(d[2 * n2 + 1][1], a1, b + 2);
        }
    }

    // ---- epilogue: partial dot over this warp's 64 cols ----
    const int q = L & 3, rq = L >> 2;
    float acc[4] = {0.f, 0.f, 0.f, 0.f};
    int rows[4];
    #pragma unroll
    for (int h = 0; h < 4; h++) rows[h] = m0 + (h >> 1) * 16 + (h & 1) * 8 + rq;

    #pragma unroll
    for (int nl = 0; nl < 8; nl++) {
        const int chunk = wn * 8 + nl;
        #pragma unroll
        for (int h = 0; h < 4; h++) {
            const int row = rows[h];
            const int byte = XS_OFF + row * 256 +
                             ((chunk ^ (row & 7)) << 4) + (q << 2);
            const float2 xf = __half22float2(*(const __half2*)(smem + byte));
            const int mt = h >> 1, pr = (h & 1) * 2;
            acc[h] += xf.x * d[nl][mt][pr] + xf.y * d[nl][mt][pr + 1];
        }
    }
    #pragma unroll
    for (int h = 0; h < 4; h++) {
        acc[h] += __shfl_xor_sync(0xffffffffu, acc[h], 1);
        acc[h] += __shfl_xor_sync(0xffffffffu, acc[h], 2);
    }
    float* redp = (float*)(smem + PART_OFF);
    if (q == 0) {
        #pragma unroll
        for (int h = 0; h < 4; h++) redp[rows[h] * 2 + wn] = acc[h];
    }
    __syncthreads();

    if (tid < DIM) {
        const float* norms = (const float*)(smem + NORM_OFF);
        out[row0 + tid] = (redp[tid * 2] + redp[tid * 2 + 1]) / norms[tid];
    }
}

// ---------------------------------------------------------------------------
extern "C" void kernel_launch(void* const* d_in, const int* in_sizes, int n_in,
                              void* d_out, int out_size) {
    const float* x = (const float*)d_in[0];
    const float* w = (const float*)d_in[1];
    int xi = 0;
    if (n_in >= 2 && in_sizes[0] == NL * 7 * 3) {
        x = (const float*)d_in[1];
        w = (const float*)d_in[0];
        xi = 1;
    }
    const int batch = in_sizes[xi] / DIM;

    cudaFuncSetAttribute(vqa_main, cudaFuncAttributeMaxDynamicSharedMemorySize,
                         SMEM_BYTES);

    build_u_kernel<<<DIM, 32>>>(w);
    build_a_kernel<<<DIM, DIM>>>();
    vqa_main<<<batch / DIM, 256, SMEM_BYTES>>>(x, (float*)d_out);
}

// round 7
// speedup vs baseline: 5.5149x; 1.0407x over previous
#include <cuda_runtime.h>
#include <cuda_fp16.h>
#include <cstdint>

#define DIM 128
#define NL 4

// ---------------------------------------------------------------------------
// Device scratch (no allocations allowed)
// ---------------------------------------------------------------------------
__device__ float g_Ur[DIM * DIM];    // U[t][j]   (row t, col j)
__device__ float g_Ui[DIM * DIM];
__device__ float g_UrT[DIM * DIM];   // U^T[j][t]
__device__ float g_UiT[DIM * DIM];
// Pre-swizzled fp16 smem image of A (B^T operand), [n=128][k=128], 256B pitch.
__device__ __align__(16) unsigned char g_Aimg[DIM * DIM * 2];  // 32 KB

// ---------------------------------------------------------------------------
// Helpers
// ---------------------------------------------------------------------------
__device__ __forceinline__ uint32_t smem_u32(const void* p) {
    uint32_t a;
    asm("{ .reg .u64 t; cvta.to.shared.u64 t, %1; cvt.u32.u64 %0, t; }"
        : "=r"(a) : "l"(p));
    return a;
}
__device__ __forceinline__ void ldsm_x4(uint32_t* r, uint32_t addr) {
    asm volatile("ldmatrix.sync.aligned.m8n8.x4.shared.b16 {%0,%1,%2,%3}, [%4];"
                 : "=r"(r[0]), "=r"(r[1]), "=r"(r[2]), "=r"(r[3]) : "r"(addr));
}
__device__ __forceinline__ void mma16816(float* d, const uint32_t* a,
                                         const uint32_t* b) {
    asm volatile(
        "mma.sync.aligned.m16n8k16.row.col.f32.f16.f16.f32 "
        "{%0,%1,%2,%3}, {%4,%5,%6,%7}, {%8,%9}, {%0,%1,%2,%3};"
        : "+f"(d[0]), "+f"(d[1]), "+f"(d[2]), "+f"(d[3])
        : "r"(a[0]), "r"(a[1]), "r"(a[2]), "r"(a[3]), "r"(b[0]), "r"(b[1]));
}

// ---------------------------------------------------------------------------
// Prep 1: build U columns.  One warp per column; state in registers.
// qubit w <-> bit (6-w) of the linear index.
// ---------------------------------------------------------------------------
__global__ __launch_bounds__(32)
void build_u_kernel(const float* __restrict__ w) {
    __shared__ float gc[28][8];
    const int L = threadIdx.x;
    const int j = blockIdx.x;
    const unsigned FULL = 0xffffffffu;

    if (L < 28) {
        const float phi = w[L * 3 + 0], th = w[L * 3 + 1], om = w[L * 3 + 2];
        float s, c;   sincosf(0.5f * th, &s, &c);
        float sa, ca; sincosf(0.5f * (phi + om), &sa, &ca);
        float sb, cb; sincosf(0.5f * (phi - om), &sb, &cb);
        gc[L][0] =  ca * c; gc[L][1] = -sa * c;   // u00
        gc[L][2] = -cb * s; gc[L][3] = -sb * s;   // u01
        gc[L][4] =  cb * s; gc[L][5] = -sb * s;   // u10
        gc[L][6] =  ca * c; gc[L][7] =  sa * c;   // u11
    }
    float sr[4], si[4];
    #pragma unroll
    for (int m = 0; m < 4; m++) {
        const int t = (m << 5) | L;
        sr[m] = (t == j) ? 1.0f : 0.0f;
        si[m] = 0.0f;
    }
    __syncwarp();

    #pragma unroll
    for (int l = 0; l < NL; l++) {
        #pragma unroll
        for (int q = 0; q < 7; q++) {
            const int g = l * 7 + q;
            const float u00r = gc[g][0], u00i = gc[g][1];
            const float u01r = gc[g][2], u01i = gc[g][3];
            const float u10r = gc[g][4], u10i = gc[g][5];
            const float u11r = gc[g][6], u11i = gc[g][7];
            const int b = 6 - q;
            if (q >= 2) {
                const int mask = 1 << b;
                const bool hi = (L & mask) != 0;
                const float c0r = hi ? u10r : u00r, c0i = hi ? u10i : u00i;
                const float c1r = hi ? u11r : u01r, c1i = hi ? u11i : u01i;
                #pragma unroll
                for (int m = 0; m < 4; m++) {
                    const float pr = __shfl_xor_sync(FULL, sr[m], mask);
                    const float pi = __shfl_xor_sync(FULL, si[m], mask);
                    const float a0r = hi ? pr : sr[m], a0i = hi ? pi : si[m];
                    const float a1r = hi ? sr[m] : pr, a1i = hi ? si[m] : pi;
                    sr[m] = c0r * a0r - c0i * a0i + c1r * a1r - c1i * a1i;
                    si[m] = c0r * a0i + c0i * a0r + c1r * a1i + c1i * a1r;
                }
            } else {
                const int d = (q == 0) ? 2 : 1;
                #pragma unroll
                for (int m = 0; m < 4; m++) {
                    if (!(m & d)) {
                        const int mh = m | d;
                        const float a0r = sr[m],  a0i = si[m];
                        const float a1r = sr[mh], a1i = si[mh];
                        sr[m]  = u00r * a0r - u00i * a0i + u01r * a1r - u01i * a1i;
                        si[m]  = u00r * a0i + u00i * a0r + u01r * a1i + u01i * a1r;
                        sr[mh] = u10r * a0r - u10i * a0i + u11r * a1r - u11i * a1i;
                        si[mh] = u10r * a0i + u10i * a0r + u11r * a1i + u11i * a1r;
                    }
                }
            }
        }
        // fused CNOT layer: new[t] = old[s(t)]; gather via shfl_idx + select
        const int r = (l % 6) + 1;
        float nr[4], ni[4];
        #pragma unroll
        for (int m = 0; m < 4; m++) {
            int s = (m << 5) | L;
            #pragma unroll
            for (int qq = 6; qq >= 0; qq--) {
                const int cb = 1 << (6 - qq);
                const int tb = 1 << (6 - ((qq + r) % 7));
                if (s & cb) s ^= tb;
            }
            const int Ls = s & 31, ms = s >> 5;
            const float v0r = __shfl_sync(FULL, sr[0], Ls);
            const float v1r = __shfl_sync(FULL, sr[1], Ls);
            const float v2r = __shfl_sync(FULL, sr[2], Ls);
            const float v3r = __shfl_sync(FULL, sr[3], Ls);
            const float v0i = __shfl_sync(FULL, si[0], Ls);
            const float v1i = __shfl_sync(FULL, si[1], Ls);
            const float v2i = __shfl_sync(FULL, si[2], Ls);
            const float v3i = __shfl_sync(FULL, si[3], Ls);
            nr[m] = (ms == 0) ? v0r : (ms == 1) ? v1r : (ms == 2) ? v2r : v3r;
            ni[m] = (ms == 0) ? v0i : (ms == 1) ? v1i : (ms == 2) ? v2i : v3i;
        }
        #pragma unroll
        for (int m = 0; m < 4; m++) { sr[m] = nr[m]; si[m] = ni[m]; }
    }
    #pragma unroll
    for (int m = 0; m < 4; m++) {
        const int t = (m << 5) | L;
        g_Ur[t * DIM + j]  = sr[m];
        g_Ui[t * DIM + j]  = si[m];
        g_UrT[j * DIM + t] = sr[m];
        g_UiT[j * DIM + t] = si[m];
    }
    cudaTriggerProgrammaticLaunchCompletion();
}

// ---------------------------------------------------------------------------
// Prep 2: A[i][j] = sum_k sgn(k)(Ur[k][i]Ur[k][j]+Ui[k][i]Ui[k][j]);
// 256 threads: k split in two halves, combined via smem.
// ---------------------------------------------------------------------------
__global__ __launch_bounds__(256)
void build_a_kernel() {
    __shared__ float cr[DIM], ci[DIM], part[2][DIM];
    const int t = threadIdx.x;
    const int j = t & 127, h = t >> 7;
    const int i = blockIdx.x;

    cudaGridDependencySynchronize();   // wait for build_u grid

    if (h == 0) {
        const float sg = (__popc(j & 0x41) & 1) ? -1.0f : 1.0f;
        cr[j] = sg * g_UrT[i * DIM + j];   // = sgn(j) * Ur[j][i], coalesced
        ci[j] = sg * g_UiT[i * DIM + j];
    }
    __syncthreads();
    float acc = 0.0f;
    const int k0 = h * 64;
    #pragma unroll 8
    for (int k = k0; k < k0 + 64; k++)
        acc += cr[k] * g_Ur[k * DIM + j] + ci[k] * g_Ui[k * DIM + j];
    part[h][j] = acc;
    __syncthreads();
    if (h == 0) {
        const __half hi = __float2half_rn(part[0][j] + part[1][j]);
        const int chi = j >> 3, sel = i & 7, within = (j & 7) * 2;
        *(__half*)(g_Aimg + i * 256 + ((chi ^ sel) << 4) + within) = hi;
    }
    cudaTriggerProgrammaticLaunchCompletion();
}

// ---------------------------------------------------------------------------
// Main kernel: CTA = 256 threads (8 warps) / 128 batch rows.
// Warp (wm, wn): M=32 rows (wm*32), N=64 cols (wn*64), K=128.
// PDL: X load/convert + norm partials run PRE-sync (overlap prep kernels).
// smem: A 32KB @0, Xs fp16 32KB @32768, norm partials (128x36 f32) @65536,
//       dot partials @83968.
// ---------------------------------------------------------------------------
#define AS_OFF   0
#define XS_OFF   32768
#define REDN_OFF 65536
#define PART_OFF 83968
#define SMEM_BYTES 84992

__global__ __launch_bounds__(256, 2)
void vqa_main(const float* __restrict__ X, float* __restrict__ out) {
    extern __shared__ __align__(16) unsigned char smem[];
    const uint32_t sb = smem_u32(smem);
    const int tid = threadIdx.x;
    const int w = tid >> 5, L = tid & 31;
    const int wm = w & 3, wn = w >> 2;
    const size_t row0 = (size_t)blockIdx.x * DIM;

    // ---- PRE-SYNC: load X, convert fp16 (swizzled), per-lane norm partials ----
    {
        float* redn = (float*)(smem + REDN_OFF);
        const float4* Xg = (const float4*)(X + row0 * DIM);
        #pragma unroll
        for (int i = 0; i < 16; i++) {
            const float4 v = Xg[i * 256 + tid];
            const int row = i * 8 + w;       // warp-uniform row
            const int c4 = L;                // float4 index within row (0..31)
            const __half2 h01 = __floats2half2_rn(v.x, v.y);
            const __half2 h23 = __floats2half2_rn(v.z, v.w);
            struct __align__(8) H4 { __half2 a, b; };
            const int byte = XS_OFF + row * 256 +
                             (((c4 >> 1) ^ (row & 7)) << 4) + ((c4 & 1) << 3);
            *(H4*)(smem + byte) = H4{h01, h23};
            redn[row * 36 + L] = v.x * v.x + v.y * v.y + v.z * v.z + v.w * v.w;
        }
    }

    cudaGridDependencySynchronize();   // wait for build_a grid (A ready)

    // ---- copy pre-swizzled A image (32KB) ----
    {
        const uint4* Ag = (const uint4*)g_Aimg;
        uint4* Asv = (uint4*)(smem + AS_OFF);
        #pragma unroll
        for (int i = 0; i < 8; i++) Asv[i * 256 + tid] = Ag[i * 256 + tid];
    }
    __syncthreads();

    // ---- GEMM: warp computes D[32 x 64] over K=128 ----
    float d[8][2][4];
    #pragma unroll
    for (int n = 0; n < 8; n++)
        #pragma unroll
        for (int m = 0; m < 2; m++)
            #pragma unroll
            for (int e = 0; e < 4; e++) d[n][m][e] = 0.0f;

    const int m0 = wm * 32;
    const int n0 = wn * 64;
    const int ra0 = m0 + (L & 15);          // a-frag rows, m-tile 0
    const int ra1 = ra0 + 16;               // m-tile 1
    const int bnr = ((L >> 4) << 3) + (L & 7);
    const int bh = (L >> 3) & 1;

    #pragma unroll 2
    for (int k = 0; k < 8; k++) {           // k-step = 16 halves
        uint32_t a0[4], a1[4];
        const int ach = 2 * k + (L >> 4);
        ldsm_x4(a0, sb + XS_OFF + ra0 * 256 + ((ach ^ (ra0 & 7)) << 4));
        ldsm_x4(a1, sb + XS_OFF + ra1 * 256 + ((ach ^ (ra1 & 7)) << 4));
        const int bch = 2 * k + bh;
        #pragma unroll
        for (int n2 = 0; n2 < 4; n2++) {
            const int nr = n0 + n2 * 16 + bnr;
            uint32_t b[4];
            ldsm_x4(b, sb + AS_OFF + nr * 256 + ((bch ^ (nr & 7)) << 4));
            mma16816(d[2 * n2][0],     a0, b);
            mma16816(d[2 * n2][1],     a1, b);
            mma16816(d[2 * n2 + 1][0], a0, b + 2);
            mma16816(d[2 * n2 + 1][1], a1, b + 2);
        }
    }

    // ---- epilogue: partial dot over this warp's 64 cols ----
    const int q = L & 3, rq = L >> 2;
    float acc[4] = {0.f, 0.f, 0.f, 0.f};
    int rows[4];
    #pragma unroll
    for (int h = 0; h < 4; h++) rows[h] = m0 + (h >> 1) * 16 + (h & 1) * 8 + rq;

    #pragma unroll
    for (int nl = 0; nl < 8; nl++) {
        const int chunk = wn * 8 + nl;
        #pragma unroll
        for (int h = 0; h < 4; h++) {
            const int row = rows[h];
            const int byte = XS_OFF + row * 256 +
                             ((chunk ^ (row & 7)) << 4) + (q << 2);
            const float2 xf = __half22float2(*(const __half2*)(smem + byte));
            const int mt = h >> 1, pr = (h & 1) * 2;
            acc[h] += xf.x * d[nl][mt][pr] + xf.y * d[nl][mt][pr + 1];
        }
    }
    #pragma unroll
    for (int h = 0; h < 4; h++) {
        acc[h] += __shfl_xor_sync(0xffffffffu, acc[h], 1);
        acc[h] += __shfl_xor_sync(0xffffffffu, acc[h], 2);
    }
    float* redp = (float*)(smem + PART_OFF);
    if (q == 0) {
        #pragma unroll
        for (int h = 0; h < 4; h++) redp[rows[h] * 2 + wn] = acc[h];
    }
    __syncthreads();

    if (tid < DIM) {
        float nrm = 0.0f;
        const float4* rn = (const float4*)(smem + REDN_OFF + tid * 144);
        #pragma unroll
        for (int c = 0; c < 8; c++) {
            const float4 p4 = rn[c];
            nrm += p4.x + p4.y + p4.z + p4.w;
        }
        out[row0 + tid] = (redp[tid * 2] + redp[tid * 2 + 1]) / nrm;
    }
}

// ---------------------------------------------------------------------------
extern "C" void kernel_launch(void* const* d_in, const int* in_sizes, int n_in,
                              void* d_out, int out_size) {
    const float* x = (const float*)d_in[0];
    const float* w = (const float*)d_in[1];
    int xi = 0;
    if (n_in >= 2 && in_sizes[0] == NL * 7 * 3) {
        x = (const float*)d_in[1];
        w = (const float*)d_in[0];
        xi = 1;
    }
    const int batch = in_sizes[xi] / DIM;
    float* outp = (float*)d_out;

    cudaFuncSetAttribute(vqa_main, cudaFuncAttributeMaxDynamicSharedMemorySize,
                         SMEM_BYTES);

    cudaLaunchAttribute at;
    at.id = cudaLaunchAttributeProgrammaticStreamSerialization;
    at.val.programmaticStreamSerializationAllowed = 1;

    build_u_kernel<<<DIM, 32>>>(w);

    {
        cudaLaunchConfig_t cfg = {};
        cfg.gridDim = dim3(DIM);
        cfg.blockDim = dim3(256);
        cfg.attrs = &at;
        cfg.numAttrs = 1;
        if (cudaLaunchKernelEx(&cfg, build_a_kernel) != cudaSuccess)
            build_a_kernel<<<DIM, 256>>>();
    }
    {
        cudaLaunchConfig_t cfg = {};
        cfg.gridDim = dim3(batch / DIM);
        cfg.blockDim = dim3(256);
        cfg.dynamicSmemBytes = SMEM_BYTES;
        cfg.attrs = &at;
        cfg.numAttrs = 1;
        if (cudaLaunchKernelEx(&cfg, vqa_main, x, outp) != cudaSuccess)
            vqa_main<<<batch / DIM, 256, SMEM_BYTES>>>(x, outp);
    }
}